// round 15
// baseline (speedup 1.0000x reference)
#include <cuda_runtime.h>
#include <cuda_fp16.h>
#include <math.h>

#define NX 128
#define NG 64
#define P  8192
#define T_STEPS 4
#define N_ITER 50
#define KAPPA 0.8f
#define LAMDA 0.9f
#define YITA  0.1f
#define NEG_SLOPE 0.01f

#define NBLK 128         // blocks; each owns 64 contiguous columns
#define CPB  64          // columns per block
#define NTHR 512         // 16 warps = 2 col-halves x 8 k-slices -> 128 regs/thread

// Device scratch (static __device__ — the sanctioned path)
__device__ __half g_M16[(size_t)P * P];   // 128 MB: M0 in mma FRAGMENT order
__device__ float g_h[P];
__device__ float g_u[3 * P];
__device__ float g_v[3 * P];
__device__ float g_dotpart[3 * NBLK];
__device__ float g_loss;
__device__ volatile unsigned g_gen;
__device__ unsigned g_count;

__device__ __forceinline__ float f_p(float v) {
    float c = fminf(fmaxf(v, -1.0f), 1.0f);
    return (c >= 0.0f) ? c : NEG_SLOPE * c;
}

// L2 access policies (createpolicy + cache_hint; valid for v4.b32)
__device__ __forceinline__ unsigned long long make_policy_keep() {
    unsigned long long pol;
    asm("createpolicy.fractional.L2::evict_last.b64 %0, 1.0;" : "=l"(pol));
    return pol;
}
__device__ __forceinline__ unsigned long long make_policy_stream() {
    unsigned long long pol;
    asm("createpolicy.fractional.L2::evict_first.b64 %0, 1.0;" : "=l"(pol));
    return pol;
}
__device__ __forceinline__ uint4 ldg_hint(const uint4* p, unsigned long long pol) {
    uint4 r;
    asm("ld.global.nc.L2::cache_hint.v4.b32 {%0,%1,%2,%3}, [%4], %5;"
        : "=r"(r.x), "=r"(r.y), "=r"(r.z), "=r"(r.w) : "l"(p), "l"(pol));
    return r;
}

// m16n8k16 f16 x f16 -> f32 mma (row.col). A rows replicated: a0=a1, a2=a3.
__device__ __forceinline__ void mma16816(float* d, unsigned p0, unsigned p1,
                                         unsigned b0, unsigned b1) {
    asm volatile(
        "mma.sync.aligned.m16n8k16.row.col.f32.f16.f16.f32 "
        "{%0,%1,%2,%3}, {%4,%5,%6,%7}, {%8,%9}, {%0,%1,%2,%3};"
        : "+f"(d[0]), "+f"(d[1]), "+f"(d[2]), "+f"(d[3])
        : "r"(p0), "r"(p0), "r"(p1), "r"(p1), "r"(b0), "r"(b1));
}

__device__ __forceinline__ unsigned pack_h2(float lo, float hi) {
    unsigned r;
    asm("cvt.rn.f16x2.f32 %0, %1, %2;" : "=r"(r) : "f"(hi), "f"(lo));
    return r;
}

// Software grid barrier; 128 blocks co-resident (1/SM).
__device__ __forceinline__ void grid_barrier() {
    if (threadIdx.x < CPB) __threadfence();
    __syncthreads();
    if (threadIdx.x == 0) {
        unsigned my = g_gen;
        if (atomicAdd(&g_count, 1) == NBLK - 1) {
            g_count = 0;
            __threadfence();
            g_gen = my + 1;
        } else {
            while (g_gen == my) __nanosleep(64);
        }
    }
    __syncthreads();
    __threadfence();
}

// Swizzle M0 (fp32, row-major) into fp16 mma-fragment order (per replay).
// Granule (b,e,w,s,tp): 512B = 32 lanes x 16B; idx = b<<10|e<<9|w<<5|s.
__global__ void k_swizzle(const float* __restrict__ M) {
    __shared__ __half tile[16][32];
    int idx = blockIdx.x;
    int s = idx & 31;
    int w = (idx >> 5) & 15;
    int e = (idx >> 9) & 1;
    int b = idx >> 10;
    int tid = threadIdx.x;             // 64 threads

    int r0 = 512 * w + 16 * s;
    int c0 = 64 * b + 32 * e;

    {
        int row = tid >> 2;
        int col8 = (tid & 3) * 8;
        const float4* src = (const float4*)(M + (size_t)(r0 + row) * P + c0 + col8);
        float4 v0 = src[0];
        float4 v1 = src[1];
        tile[row][col8 + 0] = __float2half_rn(v0.x);
        tile[row][col8 + 1] = __float2half_rn(v0.y);
        tile[row][col8 + 2] = __float2half_rn(v0.z);
        tile[row][col8 + 3] = __float2half_rn(v0.w);
        tile[row][col8 + 4] = __float2half_rn(v1.x);
        tile[row][col8 + 5] = __float2half_rn(v1.y);
        tile[row][col8 + 6] = __float2half_rn(v1.z);
        tile[row][col8 + 7] = __float2half_rn(v1.w);
    }
    __syncthreads();

    int tp = tid >> 5;
    int l  = tid & 31;
    int m  = l & 3;
    int gc = l >> 2;
    int ra = 2 * m;
    int ca = 8 * (2 * tp) + gc;
    int cb = 8 * (2 * tp + 1) + gc;

    __half2 hx = __halves2half2(tile[ra][ca], tile[ra + 1][ca]);
    __half2 hy = __halves2half2(tile[ra + 8][ca], tile[ra + 9][ca]);
    __half2 hz = __halves2half2(tile[ra][cb], tile[ra + 1][cb]);
    __half2 hw = __halves2half2(tile[ra + 8][cb], tile[ra + 9][cb]);

    uint4 out;
    out.x = *(unsigned*)&hx; out.y = *(unsigned*)&hy;
    out.z = *(unsigned*)&hz; out.w = *(unsigned*)&hw;
    *(uint4*)((char*)g_M16 + ((size_t)idx * 2 + tp) * 512 + l * 16) = out;
}

// Persistent per-timestep kernel. Warp wid = e*8+wks: col-half e (32 cols),
// k-slice wks (rows [1024*wks, +1024) = 64 ksteps). Matvec: 16 batches of
// 4 ksteps; each batch issues 8 LDG.128 (32 regs in flight) then 16 mmas.
// L2: kstep parity — even pinned (64 MB evict_last), odd streamed.
__global__ void __launch_bounds__(NTHR, 1)
k_attractor(const float* __restrict__ x, const float* __restrict__ gin,
            float* __restrict__ out, int t,
            float lam_pow, float w0, float w1, float w2) {
    __shared__ float h_sm[P];          // 32 KB full h (fp32)
    __shared__ float red[CPB][9];      // red[col][kslice], padded
    __shared__ float red2[CPB];
    __shared__ float dsum[3][4];
    __shared__ float psm[3][2];

    const int b    = blockIdx.x;
    const int tid  = threadIdx.x;
    const int lane = tid & 31;
    const int wid  = tid >> 5;         // 0..15
    const int e    = wid >> 3;         // col-half
    const int wks  = wid & 7;          // k-slice (1024 rows)
    const int m    = lane & 3;
    const int cb0  = b * CPB;
    const int nterms = t;

    const unsigned long long polK = make_policy_keep();
    const unsigned long long polS = make_policy_stream();

    // warp's contiguous 64 KB fragment span: granule idx base = b*1024+e*512+wks*64
    const char* wbase = (const char*)g_M16 +
        (size_t)(b * 1024 + e * 512 + wks * 64) * 1024 + lane * 16;
    const int k0w = 1024 * wks;

    // ---- init: h0 computed locally ----
    for (int k = tid; k < P; k += NTHR)
        h_sm[k] = f_p(gin[t * NG + (k & (NG - 1))]);
    __syncthreads();

    // ---- prologue: dot partials of h0 (t>0) ----
    if (nterms > 0) {
        if (tid < CPB) {
            int col = cb0 + tid;
            float hv = h_sm[col];
            for (int s = 0; s < nterms; ++s) {
                float w = hv * __ldg(&g_u[s * P + col]);
#pragma unroll
                for (int off = 16; off; off >>= 1)
                    w += __shfl_xor_sync(0xFFFFFFFFu, w, off);
                if (lane == 0) psm[s][wid] = w;
            }
        }
        __syncthreads();
        if (tid == 0)
            for (int s = 0; s < nterms; ++s)
                g_dotpart[s * NBLK + b] = psm[s][0] + psm[s][1];
        grid_barrier();
    }

    float hn_val = 0.f;

    for (int it = 0; it < N_ITER; ++it) {
        // ---- global dots (identical fixed-order value everywhere) ----
        if (nterms > 0 && tid < NBLK) {
            for (int s = 0; s < nterms; ++s) {
                float a = __ldcg(&g_dotpart[s * NBLK + tid]);
#pragma unroll
                for (int off = 16; off; off >>= 1)
                    a += __shfl_xor_sync(0xFFFFFFFFu, a, off);
                if (lane == 0) dsum[s][wid] = a;
            }
        }
        // ---- refresh full h ----
        if (it > 0) {
            for (int i = tid; i < P / 4; i += NTHR)
                ((float4*)h_sm)[i] = __ldcg(((const float4*)g_h) + i);
        }
        __syncthreads();

        float dots[3] = {0.f, 0.f, 0.f};
        for (int s = 0; s < nterms; ++s)
            dots[s] = ((dsum[s][0] + dsum[s][1]) + dsum[s][2]) + dsum[s][3];

        // ---- tensor-core matvec: 16 batches x (8 LDG.128 -> 16 mma) ----
        float d0[4] = {0.f, 0.f, 0.f, 0.f};
        float d1[4] = {0.f, 0.f, 0.f, 0.f};
        float d2[4] = {0.f, 0.f, 0.f, 0.f};
        float d3[4] = {0.f, 0.f, 0.f, 0.f};
#pragma unroll 2
        for (int bb = 0; bb < 16; ++bb) {
            uint4 B[8];
#pragma unroll
            for (int j = 0; j < 4; ++j) {
                int ss = bb * 4 + j;
                unsigned long long pol = (ss & 1) ? polS : polK;
                B[2 * j + 0] = ldg_hint(
                    (const uint4*)(wbase + (size_t)ss * 1024), pol);
                B[2 * j + 1] = ldg_hint(
                    (const uint4*)(wbase + (size_t)ss * 1024 + 512), pol);
            }
#pragma unroll
            for (int j = 0; j < 4; ++j) {
                int ss = bb * 4 + j;
                const float* hk = &h_sm[k0w + 16 * ss + 2 * m];
                float2 ha = *(const float2*)hk;
                float2 hb = *(const float2*)(hk + 8);
                unsigned p0 = pack_h2(ha.x, ha.y);
                unsigned p1 = pack_h2(hb.x, hb.y);
                mma16816(d0, p0, p1, B[2 * j].x, B[2 * j].y);
                mma16816(d1, p0, p1, B[2 * j].z, B[2 * j].w);
                mma16816(d2, p0, p1, B[2 * j + 1].x, B[2 * j + 1].y);
                mma16816(d3, p0, p1, B[2 * j + 1].z, B[2 * j + 1].w);
            }
        }
        // D rows identical (A replicated); lanes 0-3 carry cols 2m, 2m+1
        if (lane < 4) {
            int cl = e * 32 + 2 * m;
            red[cl + 0 * 8 + 0][wks] = d0[0]; red[cl + 0 * 8 + 1][wks] = d0[1];
            red[cl + 1 * 8 + 0][wks] = d1[0]; red[cl + 1 * 8 + 1][wks] = d1[1];
            red[cl + 2 * 8 + 0][wks] = d2[0]; red[cl + 2 * 8 + 1][wks] = d2[1];
            red[cl + 3 * 8 + 0][wks] = d3[0]; red[cl + 3 * 8 + 1][wks] = d3[1];
        }
        __syncthreads();

        // ---- column reduce over 8 k-slices: 512 threads, 8 per column ----
        {
            int c = tid >> 3, j = tid & 7;
            float s2 = red[c][j];
            s2 += __shfl_xor_sync(0xFFFFFFFFu, s2, 1);
            s2 += __shfl_xor_sync(0xFFFFFFFFu, s2, 2);
            s2 += __shfl_xor_sync(0xFFFFFFFFu, s2, 4);
            if (j == 0) red2[c] = s2;
        }
        __syncthreads();

        // ---- rank-1 corrections + pointwise update ----
        if (tid < CPB) {
            int col = cb0 + tid;
            float y = red2[tid] * lam_pow;
            if (nterms > 0) y = fmaf(w0 * dots[0], __ldg(&g_v[0 * P + col]), y);
            if (nterms > 1) y = fmaf(w1 * dots[1], __ldg(&g_v[1 * P + col]), y);
            if (nterms > 2) y = fmaf(w2 * dots[2], __ldg(&g_v[2 * P + col]), y);
            float ho = h_sm[col];
            hn_val = f_p(KAPPA * ho + ho * y);
            g_h[col] = hn_val;
            if (nterms > 0 && it < N_ITER - 1) {
                for (int s = 0; s < nterms; ++s) {
                    float w = hn_val * __ldg(&g_u[s * P + col]);
#pragma unroll
                    for (int off = 16; off; off >>= 1)
                        w += __shfl_xor_sync(0xFFFFFFFFu, w, off);
                    if (lane == 0) psm[s][wid] = w;
                }
            }
        }
        if (nterms > 0 && it < N_ITER - 1) {
            __syncthreads();
            if (tid == 0)
                for (int s = 0; s < nterms; ++s)
                    g_dotpart[s * NBLK + b] = psm[s][0] + psm[s][1];
        }
        grid_barrier();
    }

    // ---- epilogue: loss partial, store u/v, block 0 finalizes ----
    if (tid < CPB) {
        int col = cb0 + tid;
        float p = x[t * NX + (col >> 6)] * gin[t * NG + (col & (NG - 1))];
        float h = hn_val;
        if (t < 3) {
            g_u[t * P + col] = p + h;
            g_v[t * P + col] = p - h;
        }
        float a = fabsf(p - h);
#pragma unroll
        for (int off = 16; off; off >>= 1)
            a += __shfl_xor_sync(0xFFFFFFFFu, a, off);
        if (lane == 0) psm[0][wid] = a;
    }
    __syncthreads();
    if (tid == 0) g_dotpart[b] = psm[0][0] + psm[0][1];
    grid_barrier();

    if (b == 0) {
        if (tid < NBLK) {
            float a = __ldcg(&g_dotpart[tid]);
#pragma unroll
            for (int off = 16; off; off >>= 1)
                a += __shfl_xor_sync(0xFFFFFFFFu, a, off);
            if (lane == 0) dsum[0][wid] = a;
        }
        __syncthreads();
        if (tid == 0) {
            float L = (t == 0 ? 0.f : g_loss) +
                      (((dsum[0][0] + dsum[0][1]) + dsum[0][2]) + dsum[0][3]);
            g_loss = L;
            *out = L;
        }
    }
}

extern "C" void kernel_launch(void* const* d_in, const int* in_sizes, int n_in,
                              void* d_out, int out_size) {
    const float* x = (const float*)d_in[0];   // [4,128]
    const float* g = (const float*)d_in[1];   // [4,64]
    const float* M = (const float*)d_in[2];   // [8192,8192]
    float* out = (float*)d_out;
    (void)in_sizes; (void)n_in; (void)out_size;

    k_swizzle<<<128 * 2 * 16 * 32, 64>>>(M);

    for (int t = 0; t < T_STEPS; ++t) {
        float lam_pow = 1.0f;
        for (int i = 0; i < t; ++i) lam_pow *= LAMDA;
        float w[3] = {0.0f, 0.0f, 0.0f};
        for (int s = 0; s < t; ++s) {
            float lp = 1.0f;
            for (int i = 0; i < t - 1 - s; ++i) lp *= LAMDA;
            w[s] = YITA * lp;
        }
        k_attractor<<<NBLK, NTHR>>>(x, g, out, t, lam_pow, w[0], w[1], w[2]);
    }
}

// round 16
// speedup vs baseline: 1.1416x; 1.1416x over previous
#include <cuda_runtime.h>
#include <cuda_fp16.h>
#include <math.h>

#define NX 128
#define NG 64
#define P  8192
#define T_STEPS 4
#define N_ITER 50
#define KAPPA 0.8f
#define LAMDA 0.9f
#define YITA  0.1f
#define NEG_SLOPE 0.01f

#define NBLK 128         // blocks; each owns 64 contiguous columns
#define CPB  64          // columns per block
#define NTHR 1024        // 32 warps = 2 col-halves x 16 k-slices

// dynamic smem layout
#define OFF_H    0                 // 32768: full h fp32
#define OFF_H16  32768             // 16384: full h as packed half2 (uint)
#define OFF_RED  49152             // 64*17*4 = 4352
#define OFF_RED2 53504             // 256
#define DYN_BYTES 53760

// Device scratch (static __device__ — the sanctioned path)
__device__ __half g_M16[(size_t)P * P];   // 128 MB: M0 in mma FRAGMENT order
__device__ float g_h[P];
__device__ float g_u[3 * P];
__device__ float g_v[3 * P];
__device__ float g_dotpart[3 * NBLK];
__device__ float g_loss;
__device__ volatile unsigned g_gen;
__device__ unsigned g_count;

__device__ __forceinline__ float f_p(float v) {
    float c = fminf(fmaxf(v, -1.0f), 1.0f);
    return (c >= 0.0f) ? c : NEG_SLOPE * c;
}

// L2 access policies (createpolicy + cache_hint; valid for v4.b32)
__device__ __forceinline__ unsigned long long make_policy_keep() {
    unsigned long long pol;
    asm("createpolicy.fractional.L2::evict_last.b64 %0, 1.0;" : "=l"(pol));
    return pol;
}
__device__ __forceinline__ unsigned long long make_policy_stream() {
    unsigned long long pol;
    asm("createpolicy.fractional.L2::evict_first.b64 %0, 1.0;" : "=l"(pol));
    return pol;
}
__device__ __forceinline__ uint4 ldg_hint(const uint4* p, unsigned long long pol) {
    uint4 r;
    asm("ld.global.nc.L2::cache_hint.v4.b32 {%0,%1,%2,%3}, [%4], %5;"
        : "=r"(r.x), "=r"(r.y), "=r"(r.z), "=r"(r.w) : "l"(p), "l"(pol));
    return r;
}

// m16n8k16 f16 x f16 -> f32 mma (row.col). A rows replicated: a0=a1, a2=a3.
__device__ __forceinline__ void mma16816(float* d, unsigned p0, unsigned p1,
                                         unsigned b0, unsigned b1) {
    asm volatile(
        "mma.sync.aligned.m16n8k16.row.col.f32.f16.f16.f32 "
        "{%0,%1,%2,%3}, {%4,%5,%6,%7}, {%8,%9}, {%0,%1,%2,%3};"
        : "+f"(d[0]), "+f"(d[1]), "+f"(d[2]), "+f"(d[3])
        : "r"(p0), "r"(p0), "r"(p1), "r"(p1), "r"(b0), "r"(b1));
}

__device__ __forceinline__ unsigned pack_h2(float lo, float hi) {
    unsigned r;
    asm("cvt.rn.f16x2.f32 %0, %1, %2;" : "=r"(r) : "f"(hi), "f"(lo));
    return r;
}

// Software grid barrier; 128 blocks co-resident (1/SM).
__device__ __forceinline__ void grid_barrier() {
    if (threadIdx.x < CPB) __threadfence();
    __syncthreads();
    if (threadIdx.x == 0) {
        unsigned my = g_gen;
        if (atomicAdd(&g_count, 1) == NBLK - 1) {
            g_count = 0;
            __threadfence();
            g_gen = my + 1;
        } else {
            while (g_gen == my) __nanosleep(64);
        }
    }
    __syncthreads();
    __threadfence();
}

// Swizzle M0 (fp32, row-major) into fp16 mma-fragment order (per replay).
__global__ void k_swizzle(const float* __restrict__ M) {
    __shared__ __half tile[16][32];
    int idx = blockIdx.x;              // b<<10 | e<<9 | w<<5 | s
    int s = idx & 31;
    int w = (idx >> 5) & 15;
    int e = (idx >> 9) & 1;
    int b = idx >> 10;
    int tid = threadIdx.x;             // 64 threads

    int r0 = 512 * w + 16 * s;
    int c0 = 64 * b + 32 * e;

    {
        int row = tid >> 2;
        int col8 = (tid & 3) * 8;
        const float4* src = (const float4*)(M + (size_t)(r0 + row) * P + c0 + col8);
        float4 v0 = src[0];
        float4 v1 = src[1];
        tile[row][col8 + 0] = __float2half_rn(v0.x);
        tile[row][col8 + 1] = __float2half_rn(v0.y);
        tile[row][col8 + 2] = __float2half_rn(v0.z);
        tile[row][col8 + 3] = __float2half_rn(v0.w);
        tile[row][col8 + 4] = __float2half_rn(v1.x);
        tile[row][col8 + 5] = __float2half_rn(v1.y);
        tile[row][col8 + 6] = __float2half_rn(v1.z);
        tile[row][col8 + 7] = __float2half_rn(v1.w);
    }
    __syncthreads();

    int tp = tid >> 5;
    int l  = tid & 31;
    int m  = l & 3;
    int gc = l >> 2;
    int ra = 2 * m;
    int ca = 8 * (2 * tp) + gc;
    int cb = 8 * (2 * tp + 1) + gc;

    __half2 hx = __halves2half2(tile[ra][ca], tile[ra + 1][ca]);
    __half2 hy = __halves2half2(tile[ra + 8][ca], tile[ra + 9][ca]);
    __half2 hz = __halves2half2(tile[ra][cb], tile[ra + 1][cb]);
    __half2 hw = __halves2half2(tile[ra + 8][cb], tile[ra + 9][cb]);

    uint4 out;
    out.x = *(unsigned*)&hx; out.y = *(unsigned*)&hy;
    out.z = *(unsigned*)&hz; out.w = *(unsigned*)&hw;
    *(uint4*)((char*)g_M16 + ((size_t)idx * 2 + tp) * 512 + l * 16) = out;
}

// Persistent per-timestep kernel (R13 structure). Warp wid = e*16+wks.
// 32 ksteps x (2 LDG.128 + 2 LDS.32 + 4 mma). kstep 0's loads are issued
// BEFORE the grid barrier of the previous iteration (M is h-independent).
// h kept in smem both as fp32 and pre-packed half2 (kills per-kstep cvt).
__global__ void __launch_bounds__(NTHR, 1)
k_attractor(const float* __restrict__ x, const float* __restrict__ gin,
            float* __restrict__ out, int t,
            float lam_pow, float w0, float w1, float w2) {
    extern __shared__ char dyn[];
    float* h_sm = (float*)(dyn + OFF_H);
    unsigned* h16 = (unsigned*)(dyn + OFF_H16);
    float (*red)[17] = (float(*)[17])(dyn + OFF_RED);
    float* red2 = (float*)(dyn + OFF_RED2);

    __shared__ float dsum[3][4];
    __shared__ float psm[3][2];

    const int b    = blockIdx.x;
    const int tid  = threadIdx.x;
    const int lane = tid & 31;
    const int wid  = tid >> 5;
    const int e    = wid >> 4;         // col-half
    const int wks  = wid & 15;         // k-slice (512 rows = 32 ksteps)
    const int m    = lane & 3;
    const int cb0  = b * CPB;
    const int nterms = t;

    const unsigned long long polK = make_policy_keep();
    const unsigned long long polS = make_policy_stream();

    const char* wbase = (const char*)g_M16 +
        ((size_t)((b * 2 + e) * 16 + wks) * 64) * 512 + lane * 16;
    const int k0h = 256 * wks;         // half2-pair base index for this warp

    // ---- init: h0 computed locally ----
    for (int k = tid; k < P; k += NTHR)
        h_sm[k] = f_p(gin[t * NG + (k & (NG - 1))]);
    __syncthreads();

    // ---- cross-barrier prefetch of kstep 0 (M independent of h) ----
    uint4 B0p = ldg_hint((const uint4*)wbase, polK);
    uint4 B1p = ldg_hint((const uint4*)(wbase + 512), polK);

    // ---- prologue: dot partials of h0 (t>0) ----
    if (nterms > 0) {
        if (tid < CPB) {
            int col = cb0 + tid;
            float hv = h_sm[col];
            for (int s = 0; s < nterms; ++s) {
                float w = hv * __ldg(&g_u[s * P + col]);
#pragma unroll
                for (int off = 16; off; off >>= 1)
                    w += __shfl_xor_sync(0xFFFFFFFFu, w, off);
                if (lane == 0) psm[s][wid] = w;
            }
        }
        __syncthreads();
        if (tid == 0)
            for (int s = 0; s < nterms; ++s)
                g_dotpart[s * NBLK + b] = psm[s][0] + psm[s][1];
        grid_barrier();
    }

    float hn_val = 0.f;

    for (int it = 0; it < N_ITER; ++it) {
        // ---- global dots (identical fixed-order value everywhere) ----
        if (nterms > 0 && tid < NBLK) {
            for (int s = 0; s < nterms; ++s) {
                float a = __ldcg(&g_dotpart[s * NBLK + tid]);
#pragma unroll
                for (int off = 16; off; off >>= 1)
                    a += __shfl_xor_sync(0xFFFFFFFFu, a, off);
                if (lane == 0) dsum[s][wid] = a;
            }
        }
        // ---- refresh h (fp32 + packed half2) ----
        if (it > 0) {
            for (int i = tid; i < P / 4; i += NTHR) {
                float4 v = __ldcg(((const float4*)g_h) + i);
                ((float4*)h_sm)[i] = v;
                h16[2 * i + 0] = pack_h2(v.x, v.y);
                h16[2 * i + 1] = pack_h2(v.z, v.w);
            }
        } else {
            for (int i = tid; i < P / 2; i += NTHR)
                h16[i] = pack_h2(h_sm[2 * i], h_sm[2 * i + 1]);
        }
        __syncthreads();

        float dots[3] = {0.f, 0.f, 0.f};
        for (int s = 0; s < nterms; ++s)
            dots[s] = ((dsum[s][0] + dsum[s][1]) + dsum[s][2]) + dsum[s][3];

        // ---- tensor-core matvec: 32 ksteps (kstep 0 prefetched) ----
        float d0[4] = {0.f, 0.f, 0.f, 0.f};
        float d1[4] = {0.f, 0.f, 0.f, 0.f};
        float d2[4] = {0.f, 0.f, 0.f, 0.f};
        float d3[4] = {0.f, 0.f, 0.f, 0.f};
#pragma unroll 4
        for (int s = 0; s < 32; ++s) {
            uint4 B0, B1;
            if (s == 0) {
                B0 = B0p; B1 = B1p;
            } else {
                unsigned long long pol = (s & 1) ? polS : polK;
                B0 = ldg_hint((const uint4*)(wbase + (size_t)(s * 2 + 0) * 512), pol);
                B1 = ldg_hint((const uint4*)(wbase + (size_t)(s * 2 + 1) * 512), pol);
            }
            unsigned p0 = h16[k0h + 8 * s + m];
            unsigned p1 = h16[k0h + 8 * s + m + 4];
            mma16816(d0, p0, p1, B0.x, B0.y);
            mma16816(d1, p0, p1, B0.z, B0.w);
            mma16816(d2, p0, p1, B1.x, B1.y);
            mma16816(d3, p0, p1, B1.z, B1.w);
        }
        // D rows identical (A replicated); lanes 0-3 carry cols 2m, 2m+1
        if (lane < 4) {
            int cl = e * 32 + 2 * m;
            red[cl + 0 * 8 + 0][wks] = d0[0]; red[cl + 0 * 8 + 1][wks] = d0[1];
            red[cl + 1 * 8 + 0][wks] = d1[0]; red[cl + 1 * 8 + 1][wks] = d1[1];
            red[cl + 2 * 8 + 0][wks] = d2[0]; red[cl + 2 * 8 + 1][wks] = d2[1];
            red[cl + 3 * 8 + 0][wks] = d3[0]; red[cl + 3 * 8 + 1][wks] = d3[1];
        }
        __syncthreads();

        // ---- column reduce over 16 k-slices: 512 threads, 8 per column ----
        if (tid < 512) {
            int c = tid >> 3, j = tid & 7;
            float s2 = red[c][j * 2] + red[c][j * 2 + 1];
            s2 += __shfl_xor_sync(0xFFFFFFFFu, s2, 1);
            s2 += __shfl_xor_sync(0xFFFFFFFFu, s2, 2);
            s2 += __shfl_xor_sync(0xFFFFFFFFu, s2, 4);
            if (j == 0) red2[c] = s2;
        }
        __syncthreads();

        // ---- rank-1 corrections + pointwise update ----
        if (tid < CPB) {
            int col = cb0 + tid;
            float y = red2[tid] * lam_pow;
            if (nterms > 0) y = fmaf(w0 * dots[0], __ldg(&g_v[0 * P + col]), y);
            if (nterms > 1) y = fmaf(w1 * dots[1], __ldg(&g_v[1 * P + col]), y);
            if (nterms > 2) y = fmaf(w2 * dots[2], __ldg(&g_v[2 * P + col]), y);
            float ho = h_sm[col];
            hn_val = f_p(KAPPA * ho + ho * y);
            g_h[col] = hn_val;
            if (nterms > 0 && it < N_ITER - 1) {
                for (int s = 0; s < nterms; ++s) {
                    float w = hn_val * __ldg(&g_u[s * P + col]);
#pragma unroll
                    for (int off = 16; off; off >>= 1)
                        w += __shfl_xor_sync(0xFFFFFFFFu, w, off);
                    if (lane == 0) psm[s][wid] = w;
                }
            }
        }
        if (nterms > 0 && it < N_ITER - 1) {
            __syncthreads();
            if (tid == 0)
                for (int s = 0; s < nterms; ++s)
                    g_dotpart[s * NBLK + b] = psm[s][0] + psm[s][1];
        }

        // ---- prefetch next iteration's kstep 0 BEFORE the barrier ----
        if (it < N_ITER - 1) {
            B0p = ldg_hint((const uint4*)wbase, polK);
            B1p = ldg_hint((const uint4*)(wbase + 512), polK);
        }
        grid_barrier();
    }

    // ---- epilogue: loss partial, store u/v, block 0 finalizes ----
    if (tid < CPB) {
        int col = cb0 + tid;
        float p = x[t * NX + (col >> 6)] * gin[t * NG + (col & (NG - 1))];
        float h = hn_val;
        if (t < 3) {
            g_u[t * P + col] = p + h;
            g_v[t * P + col] = p - h;
        }
        float a = fabsf(p - h);
#pragma unroll
        for (int off = 16; off; off >>= 1)
            a += __shfl_xor_sync(0xFFFFFFFFu, a, off);
        if (lane == 0) psm[0][wid] = a;
    }
    __syncthreads();
    if (tid == 0) g_dotpart[b] = psm[0][0] + psm[0][1];
    grid_barrier();

    if (b == 0) {
        if (tid < NBLK) {
            float a = __ldcg(&g_dotpart[tid]);
#pragma unroll
            for (int off = 16; off; off >>= 1)
                a += __shfl_xor_sync(0xFFFFFFFFu, a, off);
            if (lane == 0) dsum[0][wid] = a;
        }
        __syncthreads();
        if (tid == 0) {
            float L = (t == 0 ? 0.f : g_loss) +
                      (((dsum[0][0] + dsum[0][1]) + dsum[0][2]) + dsum[0][3]);
            g_loss = L;
            *out = L;
        }
    }
}

extern "C" void kernel_launch(void* const* d_in, const int* in_sizes, int n_in,
                              void* d_out, int out_size) {
    const float* x = (const float*)d_in[0];   // [4,128]
    const float* g = (const float*)d_in[1];   // [4,64]
    const float* M = (const float*)d_in[2];   // [8192,8192]
    float* out = (float*)d_out;
    (void)in_sizes; (void)n_in; (void)out_size;

    cudaFuncSetAttribute(k_attractor,
                         cudaFuncAttributeMaxDynamicSharedMemorySize, DYN_BYTES);

    k_swizzle<<<128 * 2 * 16 * 32, 64>>>(M);

    for (int t = 0; t < T_STEPS; ++t) {
        float lam_pow = 1.0f;
        for (int i = 0; i < t; ++i) lam_pow *= LAMDA;
        float w[3] = {0.0f, 0.0f, 0.0f};
        for (int s = 0; s < t; ++s) {
            float lp = 1.0f;
            for (int i = 0; i < t - 1 - s; ++i) lp *= LAMDA;
            w[s] = YITA * lp;
        }
        k_attractor<<<NBLK, NTHR, DYN_BYTES>>>(x, g, out, t,
                                               lam_pow, w[0], w[1], w[2]);
    }
}

// round 17
// speedup vs baseline: 1.1651x; 1.0205x over previous
#include <cuda_runtime.h>
#include <cuda_fp16.h>
#include <math.h>

#define NX 128
#define NG 64
#define P  8192
#define T_STEPS 4
#define N_ITER 50
#define KAPPA 0.8f
#define LAMDA 0.9f
#define YITA  0.1f
#define NEG_SLOPE 0.01f

#define NBLK 256         // blocks; 2 per SM; each owns 32 contiguous columns
#define CPB  32          // columns per block
#define NTHR 512         // 16 warps = 16 k-slices

// Device scratch (static __device__ — the sanctioned path)
__device__ __half g_M16[(size_t)P * P];   // 128 MB: M0 in mma FRAGMENT order
__device__ float g_h[P];
__device__ float g_u[3 * P];
__device__ float g_v[3 * P];
__device__ float g_dotpart[3 * NBLK];     // per-block dot partials (+ loss reuse)
__device__ float g_loss;
__device__ volatile unsigned g_gen;
__device__ unsigned g_count;

__device__ __forceinline__ float f_p(float v) {
    float c = fminf(fmaxf(v, -1.0f), 1.0f);
    return (c >= 0.0f) ? c : NEG_SLOPE * c;
}

// L2 access policies (createpolicy + cache_hint; valid for v4.b32)
__device__ __forceinline__ unsigned long long make_policy_keep() {
    unsigned long long pol;
    asm("createpolicy.fractional.L2::evict_last.b64 %0, 1.0;" : "=l"(pol));
    return pol;
}
__device__ __forceinline__ unsigned long long make_policy_stream() {
    unsigned long long pol;
    asm("createpolicy.fractional.L2::evict_first.b64 %0, 1.0;" : "=l"(pol));
    return pol;
}
__device__ __forceinline__ uint4 ldg_hint(const uint4* p, unsigned long long pol) {
    uint4 r;
    asm("ld.global.nc.L2::cache_hint.v4.b32 {%0,%1,%2,%3}, [%4], %5;"
        : "=r"(r.x), "=r"(r.y), "=r"(r.z), "=r"(r.w) : "l"(p), "l"(pol));
    return r;
}

// m16n8k16 f16 x f16 -> f32 mma (row.col). A rows replicated: a0=a1, a2=a3.
__device__ __forceinline__ void mma16816(float* d, unsigned p0, unsigned p1,
                                         unsigned b0, unsigned b1) {
    asm volatile(
        "mma.sync.aligned.m16n8k16.row.col.f32.f16.f16.f32 "
        "{%0,%1,%2,%3}, {%4,%5,%6,%7}, {%8,%9}, {%0,%1,%2,%3};"
        : "+f"(d[0]), "+f"(d[1]), "+f"(d[2]), "+f"(d[3])
        : "r"(p0), "r"(p0), "r"(p1), "r"(p1), "r"(b0), "r"(b1));
}

__device__ __forceinline__ unsigned pack_h2(float lo, float hi) {
    unsigned r;
    asm("cvt.rn.f16x2.f32 %0, %1, %2;" : "=r"(r) : "f"(hi), "f"(lo));
    return r;
}

// Software grid barrier; 256 blocks co-resident (2/SM, occupancy-proven).
__device__ __forceinline__ void grid_barrier() {
    if (threadIdx.x < CPB) __threadfence();   // only tid<32 write globals
    __syncthreads();
    if (threadIdx.x == 0) {
        unsigned my = g_gen;
        if (atomicAdd(&g_count, 1) == NBLK - 1) {
            g_count = 0;
            __threadfence();
            g_gen = my + 1;
        } else {
            while (g_gen == my) __nanosleep(64);
        }
    }
    __syncthreads();
    __threadfence();
}

// Swizzle M0 (fp32, row-major) into fp16 mma-fragment order (per replay).
// Granule (b,e,w,s,tp): 512B; idx = b<<10|e<<9|w<<5|s; addr=(idx*2+tp)*512.
__global__ void k_swizzle(const float* __restrict__ M) {
    __shared__ __half tile[16][32];
    int idx = blockIdx.x;
    int s = idx & 31;
    int w = (idx >> 5) & 15;
    int e = (idx >> 9) & 1;
    int b = idx >> 10;
    int tid = threadIdx.x;             // 64 threads

    int r0 = 512 * w + 16 * s;
    int c0 = 64 * b + 32 * e;

    {
        int row = tid >> 2;
        int col8 = (tid & 3) * 8;
        const float4* src = (const float4*)(M + (size_t)(r0 + row) * P + c0 + col8);
        float4 v0 = src[0];
        float4 v1 = src[1];
        tile[row][col8 + 0] = __float2half_rn(v0.x);
        tile[row][col8 + 1] = __float2half_rn(v0.y);
        tile[row][col8 + 2] = __float2half_rn(v0.z);
        tile[row][col8 + 3] = __float2half_rn(v0.w);
        tile[row][col8 + 4] = __float2half_rn(v1.x);
        tile[row][col8 + 5] = __float2half_rn(v1.y);
        tile[row][col8 + 6] = __float2half_rn(v1.z);
        tile[row][col8 + 7] = __float2half_rn(v1.w);
    }
    __syncthreads();

    int tp = tid >> 5;
    int l  = tid & 31;
    int m  = l & 3;
    int gc = l >> 2;
    int ra = 2 * m;
    int ca = 8 * (2 * tp) + gc;
    int cb = 8 * (2 * tp + 1) + gc;

    __half2 hx = __halves2half2(tile[ra][ca], tile[ra + 1][ca]);
    __half2 hy = __halves2half2(tile[ra + 8][ca], tile[ra + 9][ca]);
    __half2 hz = __halves2half2(tile[ra][cb], tile[ra + 1][cb]);
    __half2 hw = __halves2half2(tile[ra + 8][cb], tile[ra + 9][cb]);

    uint4 out;
    out.x = *(unsigned*)&hx; out.y = *(unsigned*)&hy;
    out.z = *(unsigned*)&hz; out.w = *(unsigned*)&hw;
    *(uint4*)((char*)g_M16 + ((size_t)idx * 2 + tp) * 512 + l * 16) = out;
}

// Persistent per-timestep kernel, 2 CTAs/SM. Block b owns 32 columns
// [b*32, b*32+32); warp wks covers rows [512*wks, +512) = 32 ksteps of
// (2 LDG.128 + 4 mma). L2: kstep parity — even pinned, odd streamed.
__global__ void __launch_bounds__(NTHR, 2)
k_attractor(const float* __restrict__ x, const float* __restrict__ gin,
            float* __restrict__ out, int t,
            float lam_pow, float w0, float w1, float w2) {
    __shared__ float h_sm[P];          // 32 KB full h
    __shared__ float red[CPB][17];     // red[col][kslice], padded
    __shared__ float red2[CPB];
    __shared__ float dsum[3][8];       // dot reduce: 8 warp sums per term

    const int b    = blockIdx.x;
    const int tid  = threadIdx.x;
    const int lane = tid & 31;
    const int wid  = tid >> 5;         // 0..15 = k-slice
    const int m    = lane & 3;
    const int cb0  = b * CPB;
    const int nterms = t;

    const unsigned long long polK = make_policy_keep();
    const unsigned long long polS = make_policy_stream();

    // warp's fragment span: (b*512 + wks*32) granule-pairs of 1024B
    const char* wbase = (const char*)g_M16 +
        (size_t)(b * 512 + wid * 32) * 1024 + lane * 16;
    const int k0w = 512 * wid;

    // ---- init: h0 computed locally ----
    for (int k = tid; k < P; k += NTHR)
        h_sm[k] = f_p(gin[t * NG + (k & (NG - 1))]);
    __syncthreads();

    // ---- prologue: dot partials of h0 (t>0); single warp, pure shuffle ----
    if (nterms > 0) {
        if (tid < CPB) {
            int col = cb0 + tid;
            float hv = h_sm[col];
            for (int s = 0; s < nterms; ++s) {
                float w = hv * __ldg(&g_u[s * P + col]);
#pragma unroll
                for (int off = 16; off; off >>= 1)
                    w += __shfl_xor_sync(0xFFFFFFFFu, w, off);
                if (lane == 0) g_dotpart[s * NBLK + b] = w;
            }
        }
        grid_barrier();
    }

    float hn_val = 0.f;

    for (int it = 0; it < N_ITER; ++it) {
        // ---- global dots: 256 partials -> 8 warp sums -> scalar ----
        if (nterms > 0 && tid < NBLK) {
            for (int s = 0; s < nterms; ++s) {
                float a = __ldcg(&g_dotpart[s * NBLK + tid]);
#pragma unroll
                for (int off = 16; off; off >>= 1)
                    a += __shfl_xor_sync(0xFFFFFFFFu, a, off);
                if (lane == 0) dsum[s][wid] = a;
            }
        }
        // ---- refresh full h ----
        if (it > 0) {
            for (int i = tid; i < P / 4; i += NTHR)
                ((float4*)h_sm)[i] = __ldcg(((const float4*)g_h) + i);
        }
        __syncthreads();

        float dots[3] = {0.f, 0.f, 0.f};
        for (int s = 0; s < nterms; ++s)
            dots[s] = ((dsum[s][0] + dsum[s][1]) + (dsum[s][2] + dsum[s][3])) +
                      ((dsum[s][4] + dsum[s][5]) + (dsum[s][6] + dsum[s][7]));

        // ---- tensor-core matvec: 32 ksteps x (2 LDG.128 + 4 mma) ----
        float d0[4] = {0.f, 0.f, 0.f, 0.f};
        float d1[4] = {0.f, 0.f, 0.f, 0.f};
        float d2[4] = {0.f, 0.f, 0.f, 0.f};
        float d3[4] = {0.f, 0.f, 0.f, 0.f};
#pragma unroll 4
        for (int s = 0; s < 32; ++s) {
            unsigned long long pol = (s & 1) ? polS : polK;
            uint4 B0 = ldg_hint((const uint4*)(wbase + (size_t)(s * 2 + 0) * 512), pol);
            uint4 B1 = ldg_hint((const uint4*)(wbase + (size_t)(s * 2 + 1) * 512), pol);
            const float* hk = &h_sm[k0w + 16 * s + 2 * m];
            float2 ha = *(const float2*)hk;
            float2 hb = *(const float2*)(hk + 8);
            unsigned p0 = pack_h2(ha.x, ha.y);
            unsigned p1 = pack_h2(hb.x, hb.y);
            mma16816(d0, p0, p1, B0.x, B0.y);
            mma16816(d1, p0, p1, B0.z, B0.w);
            mma16816(d2, p0, p1, B1.x, B1.y);
            mma16816(d3, p0, p1, B1.z, B1.w);
        }
        // D rows identical (A replicated); lanes 0-3 carry cols 2m, 2m+1
        // of each ntile n (cols n*8 + {0..7} within the block's 32)
        if (lane < 4) {
            int cl = 2 * m;
            red[cl + 0 * 8 + 0][wid] = d0[0]; red[cl + 0 * 8 + 1][wid] = d0[1];
            red[cl + 1 * 8 + 0][wid] = d1[0]; red[cl + 1 * 8 + 1][wid] = d1[1];
            red[cl + 2 * 8 + 0][wid] = d2[0]; red[cl + 2 * 8 + 1][wid] = d2[1];
            red[cl + 3 * 8 + 0][wid] = d3[0]; red[cl + 3 * 8 + 1][wid] = d3[1];
        }
        __syncthreads();

        // ---- column reduce over 16 k-slices: 512 threads, 16 per column ----
        {
            int c = tid >> 4, j = tid & 15;
            float s2 = red[c][j];
            s2 += __shfl_xor_sync(0xFFFFFFFFu, s2, 1);
            s2 += __shfl_xor_sync(0xFFFFFFFFu, s2, 2);
            s2 += __shfl_xor_sync(0xFFFFFFFFu, s2, 4);
            s2 += __shfl_xor_sync(0xFFFFFFFFu, s2, 8);
            if (j == 0) red2[c] = s2;
        }
        __syncthreads();

        // ---- rank-1 corrections + pointwise update (single warp) ----
        if (tid < CPB) {
            int col = cb0 + tid;
            float y = red2[tid] * lam_pow;
            if (nterms > 0) y = fmaf(w0 * dots[0], __ldg(&g_v[0 * P + col]), y);
            if (nterms > 1) y = fmaf(w1 * dots[1], __ldg(&g_v[1 * P + col]), y);
            if (nterms > 2) y = fmaf(w2 * dots[2], __ldg(&g_v[2 * P + col]), y);
            float ho = h_sm[col];
            hn_val = f_p(KAPPA * ho + ho * y);
            g_h[col] = hn_val;
            // publish dot partials of new h (skip after last iteration)
            if (nterms > 0 && it < N_ITER - 1) {
                for (int s = 0; s < nterms; ++s) {
                    float w = hn_val * __ldg(&g_u[s * P + col]);
#pragma unroll
                    for (int off = 16; off; off >>= 1)
                        w += __shfl_xor_sync(0xFFFFFFFFu, w, off);
                    if (lane == 0) g_dotpart[s * NBLK + b] = w;
                }
            }
        }
        grid_barrier();
    }

    // ---- epilogue: loss partial, store u/v, block 0 finalizes ----
    if (tid < CPB) {
        int col = cb0 + tid;
        float p = x[t * NX + (col >> 6)] * gin[t * NG + (col & (NG - 1))];
        float h = hn_val;
        if (t < 3) {
            g_u[t * P + col] = p + h;
            g_v[t * P + col] = p - h;
        }
        float a = fabsf(p - h);
#pragma unroll
        for (int off = 16; off; off >>= 1)
            a += __shfl_xor_sync(0xFFFFFFFFu, a, off);
        if (lane == 0) g_dotpart[b] = a;
    }
    grid_barrier();

    if (b == 0) {
        if (tid < NBLK) {
            float a = __ldcg(&g_dotpart[tid]);
#pragma unroll
            for (int off = 16; off; off >>= 1)
                a += __shfl_xor_sync(0xFFFFFFFFu, a, off);
            if (lane == 0) dsum[0][wid] = a;
        }
        __syncthreads();
        if (tid == 0) {
            float L = (t == 0 ? 0.f : g_loss) +
                      (((dsum[0][0] + dsum[0][1]) + (dsum[0][2] + dsum[0][3])) +
                       ((dsum[0][4] + dsum[0][5]) + (dsum[0][6] + dsum[0][7])));
            g_loss = L;
            *out = L;
        }
    }
}

extern "C" void kernel_launch(void* const* d_in, const int* in_sizes, int n_in,
                              void* d_out, int out_size) {
    const float* x = (const float*)d_in[0];   // [4,128]
    const float* g = (const float*)d_in[1];   // [4,64]
    const float* M = (const float*)d_in[2];   // [8192,8192]
    float* out = (float*)d_out;
    (void)in_sizes; (void)n_in; (void)out_size;

    k_swizzle<<<128 * 2 * 16 * 32, 64>>>(M);

    for (int t = 0; t < T_STEPS; ++t) {
        float lam_pow = 1.0f;
        for (int i = 0; i < t; ++i) lam_pow *= LAMDA;
        float w[3] = {0.0f, 0.0f, 0.0f};
        for (int s = 0; s < t; ++s) {
            float lp = 1.0f;
            for (int i = 0; i < t - 1 - s; ++i) lp *= LAMDA;
            w[s] = YITA * lp;
        }
        k_attractor<<<NBLK, NTHR>>>(x, g, out, t, lam_pow, w[0], w[1], w[2]);
    }
}